// round 13
// baseline (speedup 1.0000x reference)
#include <cuda_runtime.h>
#include <cstdint>
#include <cstddef>

// Problem dims
#define BB 16
#define TT 4096
#define DD 512
#define HH 512
#define NC 1536   // 3*H

typedef unsigned long long ull;

// ---------------- scratch (device globals: no runtime allocation allowed) ---
__device__ float g_xk[(size_t)BB * TT * NC];   // 402 MB: x @ kernel + bias0
__device__ float g_acc[2][8][16][6][HH];       // 3.1 MB: K-slice partials
                                               // [parity][group][srcCTA][g*2+b][unit]
__device__ int   g_ctr[8 * TT];                // per-group per-step arrivals

// ---------------- f32x2 packed-math helpers (sm_103a) -----------------------
__device__ __forceinline__ ull pk2(float lo, float hi) {
    ull r;
    asm("mov.b64 %0, {%1, %2};" : "=l"(r) : "f"(lo), "f"(hi));
    return r;
}
__device__ __forceinline__ void unpk2(float& lo, float& hi, ull v) {
    asm("mov.b64 {%0, %1}, %2;" : "=f"(lo), "=f"(hi) : "l"(v));
}
__device__ __forceinline__ ull fma2(ull a, ull b, ull c) {
    ull d;
    asm("fma.rn.f32x2 %0, %1, %2, %3;" : "=l"(d) : "l"(a), "l"(b), "l"(c));
    return d;
}
__device__ __forceinline__ float sigmoid_f(float x) {
    return 1.f / (1.f + __expf(-x));
}
__device__ __forceinline__ float tanh_f(float x) {
    float e = __expf(2.f * x);
    return (e - 1.f) / (e + 1.f);
}
__device__ __forceinline__ uint32_t f2tf32(float f) {
    uint32_t r;
    asm("cvt.rna.tf32.f32 %0, %1;" : "=r"(r) : "f"(f));
    return r;
}
__device__ __forceinline__ void mma_tf32(float* c,
                                         uint32_t a0, uint32_t a1,
                                         uint32_t a2, uint32_t a3,
                                         uint32_t b0, uint32_t b1) {
    asm volatile(
        "mma.sync.aligned.m16n8k8.row.col.f32.tf32.tf32.f32 "
        "{%0,%1,%2,%3}, {%4,%5,%6,%7}, {%8,%9}, {%0,%1,%2,%3};"
        : "+f"(c[0]), "+f"(c[1]), "+f"(c[2]), "+f"(c[3])
        : "r"(a0), "r"(a1), "r"(a2), "r"(a3), "r"(b0), "r"(b1));
}

// ============================================================================
// Phase 1: xk = x @ W + bias0  (tf32 tensor cores, unchanged from R12)
// ============================================================================
#define GBM 128
#define GBN 64
#define GBK 32
#define ASTR 36
#define BSTR 68

__global__ void __launch_bounds__(256, 2)
gemm_xk_tf32(const float* __restrict__ A,
             const float* __restrict__ W,
             const float* __restrict__ bias)
{
    __shared__ float As[2][GBM][ASTR];
    __shared__ float Bs[2][GBK][BSTR];

    const int bm   = blockIdx.y * GBM;
    const int bn   = blockIdx.x * GBN;
    const int tid  = threadIdx.x;
    const int wid  = tid >> 5;
    const int lane = tid & 31;
    const int wm   = (wid & 3) * 32;
    const int wn   = (wid >> 2) * 32;
    const int lr   = lane >> 2;
    const int lc   = lane & 3;

    float acc[2][4][4];
#pragma unroll
    for (int mi = 0; mi < 2; mi++)
#pragma unroll
        for (int ni = 0; ni < 4; ni++)
#pragma unroll
            for (int q = 0; q < 4; q++) acc[mi][ni][q] = 0.f;

    float4 aref[4], bref[2];

#pragma unroll
    for (int i = 0; i < 4; i++) {
        int f = tid + i * 256, row = f >> 3, c4 = (f & 7) << 2;
        aref[i] = *(const float4*)&A[(size_t)(bm + row) * DD + c4];
    }
#pragma unroll
    for (int i = 0; i < 2; i++) {
        int f = tid + i * 256, k = f >> 4, n4 = (f & 15) << 2;
        bref[i] = *(const float4*)&W[(size_t)k * NC + bn + n4];
    }
#pragma unroll
    for (int i = 0; i < 4; i++) {
        int f = tid + i * 256, row = f >> 3, c4 = (f & 7) << 2;
        *(float4*)&As[0][row][c4] = aref[i];
    }
#pragma unroll
    for (int i = 0; i < 2; i++) {
        int f = tid + i * 256, k = f >> 4, n4 = (f & 15) << 2;
        *(float4*)&Bs[0][k][n4] = bref[i];
    }
    __syncthreads();

    const int NKT = DD / GBK;
    for (int kt = 0; kt < NKT; kt++) {
        const int cur = kt & 1;

        if (kt < NKT - 1) {
            int kb = (kt + 1) * GBK;
#pragma unroll
            for (int i = 0; i < 4; i++) {
                int f = tid + i * 256, row = f >> 3, c4 = (f & 7) << 2;
                aref[i] = *(const float4*)&A[(size_t)(bm + row) * DD + kb + c4];
            }
#pragma unroll
            for (int i = 0; i < 2; i++) {
                int f = tid + i * 256, k = f >> 4, n4 = (f & 15) << 2;
                bref[i] = *(const float4*)&W[(size_t)(kb + k) * NC + bn + n4];
            }
        }

#pragma unroll
        for (int k8 = 0; k8 < 4; k8++) {
            uint32_t bf[4][2];
#pragma unroll
            for (int ni = 0; ni < 4; ni++) {
                int cb = wn + ni * 8;
                bf[ni][0] = f2tf32(Bs[cur][k8 * 8 + lc    ][cb + lr]);
                bf[ni][1] = f2tf32(Bs[cur][k8 * 8 + lc + 4][cb + lr]);
            }
#pragma unroll
            for (int mi = 0; mi < 2; mi++) {
                int rb = wm + mi * 16;
                uint32_t a0 = f2tf32(As[cur][rb + lr    ][k8 * 8 + lc    ]);
                uint32_t a1 = f2tf32(As[cur][rb + lr + 8][k8 * 8 + lc    ]);
                uint32_t a2 = f2tf32(As[cur][rb + lr    ][k8 * 8 + lc + 4]);
                uint32_t a3 = f2tf32(As[cur][rb + lr + 8][k8 * 8 + lc + 4]);
#pragma unroll
                for (int ni = 0; ni < 4; ni++)
                    mma_tf32(acc[mi][ni], a0, a1, a2, a3, bf[ni][0], bf[ni][1]);
            }
        }

        if (kt < NKT - 1) {
            __syncthreads();
#pragma unroll
            for (int i = 0; i < 4; i++) {
                int f = tid + i * 256, row = f >> 3, c4 = (f & 7) << 2;
                *(float4*)&As[cur ^ 1][row][c4] = aref[i];
            }
#pragma unroll
            for (int i = 0; i < 2; i++) {
                int f = tid + i * 256, k = f >> 4, n4 = (f & 15) << 2;
                *(float4*)&Bs[cur ^ 1][k][n4] = bref[i];
            }
            __syncthreads();
        }
    }

#pragma unroll
    for (int mi = 0; mi < 2; mi++) {
#pragma unroll
        for (int ni = 0; ni < 4; ni++) {
            int r0 = bm + wm + mi * 16 + lr;
            int c0 = bn + wn + ni * 8 + lc * 2;
            float bz0 = bias[c0], bz1 = bias[c0 + 1];
            float2 v0 = make_float2(acc[mi][ni][0] + bz0, acc[mi][ni][1] + bz1);
            float2 v1 = make_float2(acc[mi][ni][2] + bz0, acc[mi][ni][3] + bz1);
            *(float2*)&g_xk[(size_t)r0 * NC + c0]       = v0;
            *(float2*)&g_xk[(size_t)(r0 + 8) * NC + c0] = v1;
        }
    }
}

// ============================================================================
// Phase 2: persistent GRU recurrence — K-SLICED U, local-h design.
//   8 groups x 16 CTAs; group g owns batches {2g,2g+1}. CTA c owns U K-rows
//   [32c,32c+32) for ALL 1536 columns: thread tid holds U[k-slice][g*512+tid]
//   for the 3 gates = 48 f32x2 regs (same budget as before).
//   Per step:
//     dot: 6 partials (3 gates x 2 batches) for column tid over own K-slice;
//          h read from LOCAL smem (the CTA's own 64 h values = its K-slice).
//     STG partials (coalesced) to ping-pong g_acc[par][grp][c][g*2+b][tid]
//     __syncthreads; tid0 red.release.gpu ctr[t]  (HB via the barrier)
//     gate threads (tid<64: batch=tid>>5, unit j=32c+(tid&31)): acquire-poll
//          ctr[t]==16, gather 48 coalesced partials, sum, gates, h' -> SMEM
//          h_s (local!), out stores; __syncthreads.
//   h NEVER crosses CTAs. Ping-pong safety: a CTA reaching step t+2 STGs has
//   passed poll(t+1), which required every CTA's release(t+1), which is after
//   their post-gate(t) __syncthreads, i.e. after all acc(t) reads (HB chain).
// ============================================================================
__global__ void __launch_bounds__(512, 1)
gru_rec_kernel(const float* __restrict__ RK,
               const float* __restrict__ bias,
               float* __restrict__ out)
{
    __shared__ float h_s[2][32];           // local h: [batch][unit-in-slice]

    const int bx  = blockIdx.x;
    const int g   = bx >> 4;               // group 0..7
    const int c   = bx & 15;               // cta-in-group 0..15
    const int tid = threadIdx.x;
    const int k0  = c * 32;                // first K-row owned
    const int b0  = g * 2;                 // first global batch

    // ---- Load U K-slice into registers: ureg[gate][i] = U[k0+2i..+1][gate*512+tid]
    ull ureg[3][16];
#pragma unroll
    for (int gi = 0; gi < 3; gi++)
#pragma unroll
        for (int i = 0; i < 16; i++) {
            int k = k0 + 2 * i;
            float lo = RK[(size_t)k       * NC + gi * HH + tid];
            float hi = RK[(size_t)(k + 1) * NC + gi * HH + tid];
            ureg[gi][i] = pk2(lo, hi);
        }

    // gate-thread state (tid < 64): batch gb, unit j = k0 + jl
    const int gb = tid >> 5;               // 0..1
    const int jl = tid & 31;
    const int j  = k0 + jl;

    float rbz = 0.f, rbr = 0.f, rbh = 0.f, h_old = 0.f;
    float xz = 0.f, xr = 0.f, xh = 0.f;
    size_t xbase0 = 0;
    if (tid < 64) {
        rbz = bias[NC + 0 * HH + j];
        rbr = bias[NC + 1 * HH + j];
        rbh = bias[NC + 2 * HH + j];
        xbase0 = ((size_t)(b0 + gb) * TT) * NC + j;
        xz = g_xk[xbase0];
        xr = g_xk[xbase0 + HH];
        xh = g_xk[xbase0 + 2 * HH];
    }
    if (tid < 64) h_s[gb][jl] = 0.f;       // h0 = zeros
    __syncthreads();

    int* ctr = &g_ctr[g * TT];

    for (int t = 0; t < TT; t++) {
        const int par = t & 1;

        // ---- dot: partials for column tid over own K-slice (h LOCAL) ------
        {
            const ull* h0 = (const ull*)h_s[0];
            const ull* h1 = (const ull*)h_s[1];
            ull a00 = 0, a01 = 0, a02 = 0, a10 = 0, a11 = 0, a12 = 0;
#pragma unroll
            for (int i = 0; i < 16; i++) {
                ull hh0 = h0[i];           // broadcast LDS.64
                ull hh1 = h1[i];
                a00 = fma2(ureg[0][i], hh0, a00);
                a01 = fma2(ureg[1][i], hh0, a01);
                a02 = fma2(ureg[2][i], hh0, a02);
                a10 = fma2(ureg[0][i], hh1, a10);
                a11 = fma2(ureg[1][i], hh1, a11);
                a12 = fma2(ureg[2][i], hh1, a12);
            }
            float lo, hi, p;
            float* dst = &g_acc[par][g][c][0][tid];
            unpk2(lo, hi, a00); p = lo + hi;
            asm volatile("st.global.cg.f32 [%0], %1;" :: "l"(dst + 0 * HH), "f"(p) : "memory");
            unpk2(lo, hi, a10); p = lo + hi;
            asm volatile("st.global.cg.f32 [%0], %1;" :: "l"(dst + 1 * HH), "f"(p) : "memory");
            unpk2(lo, hi, a01); p = lo + hi;
            asm volatile("st.global.cg.f32 [%0], %1;" :: "l"(dst + 2 * HH), "f"(p) : "memory");
            unpk2(lo, hi, a11); p = lo + hi;
            asm volatile("st.global.cg.f32 [%0], %1;" :: "l"(dst + 3 * HH), "f"(p) : "memory");
            unpk2(lo, hi, a02); p = lo + hi;
            asm volatile("st.global.cg.f32 [%0], %1;" :: "l"(dst + 4 * HH), "f"(p) : "memory");
            unpk2(lo, hi, a12); p = lo + hi;
            asm volatile("st.global.cg.f32 [%0], %1;" :: "l"(dst + 5 * HH), "f"(p) : "memory");
        }
        __syncthreads();                   // all STGs program-ordered before release
        if (tid == 0)
            asm volatile("red.release.gpu.global.add.s32 [%0], %1;"
                         :: "l"(&ctr[t]), "r"(1) : "memory");

        // ---- gate threads: poll, gather 16 K-slice partials/gate, gates ----
        if (tid < 64) {
            int cv;
            do {
                asm volatile("ld.acquire.gpu.global.b32 %0, [%1];"
                             : "=r"(cv) : "l"(&ctr[t]) : "memory");
            } while (cv != 16);

            float s0 = 0.f, s1 = 0.f, s2 = 0.f;
            const float* src = &g_acc[par][g][0][gb][j];   // row gb = gate0/batch gb
#pragma unroll
            for (int cc = 0; cc < 16; cc++) {
                const float* p = src + (size_t)cc * (6 * HH);
                float v0, v1, v2;
                asm volatile("ld.global.cg.f32 %0, [%1];" : "=f"(v0) : "l"(p)          : "memory");
                asm volatile("ld.global.cg.f32 %0, [%1];" : "=f"(v1) : "l"(p + 2 * HH) : "memory");
                asm volatile("ld.global.cg.f32 %0, [%1];" : "=f"(v2) : "l"(p + 4 * HH) : "memory");
                s0 += v0; s1 += v1; s2 += v2;
            }

            float z    = sigmoid_f(xz + s0 + rbz);
            float r    = sigmoid_f(xr + s1 + rbr);
            float cand = tanh_f(xh + r * (s2 + rbh));
            float hn   = z * h_old + (1.f - z) * cand;
            h_old = hn;

            h_s[gb][jl] = hn;              // local handoff — no L2 hop!

            out[((size_t)(b0 + gb) * TT + t) * HH + j] = hn;
            if (t == TT - 1)
                out[(size_t)BB * TT * HH + (size_t)(b0 + gb) * HH + j] = hn;

            // prefetch next step's xk
            {
                size_t nb = xbase0 + (size_t)((t + 1 < TT) ? t + 1 : t) * NC;
                xz = g_xk[nb];
                xr = g_xk[nb + HH];
                xh = g_xk[nb + 2 * HH];
            }
        }
        __syncthreads();                   // h_s ready for next dot
    }
}

// ============================================================================
extern "C" void kernel_launch(void* const* d_in, const int* in_sizes, int n_in,
                              void* d_out, int out_size)
{
    const float* x    = (const float*)d_in[0];   // [16,4096,512]
    const float* Wk   = (const float*)d_in[1];   // [512,1536]
    const float* RK   = (const float*)d_in[2];   // [512,1536]
    const float* bias = (const float*)d_in[3];   // [2,1536]
    float* out = (float*)d_out;                  // outputs ++ state

    // Zero the arrival counters (memset node; re-zeroed per graph replay).
    void* ctr_ptr = nullptr;
    cudaGetSymbolAddress(&ctr_ptr, g_ctr);
    cudaMemsetAsync(ctr_ptr, 0, sizeof(int) * 8 * TT);

    // Phase 1: input projection GEMM (tf32 tensor cores).
    dim3 grid1(NC / GBN, (BB * TT) / GBM);
    gemm_xk_tf32<<<grid1, 256>>>(x, Wk, bias);

    // Phase 2: persistent recurrence (K-sliced U, local h).
    gru_rec_kernel<<<128, 512>>>(RK, bias, out);
}